// round 13
// baseline (speedup 1.0000x reference)
#include <cuda_runtime.h>

// QuantumLayer collapses analytically to out[b] = cos(x[b,0] + weights[0]):
//  - RY(w)RY(x)|0> = RY(x+w)|0> (angles add; product state).
//  - Qubit 0 is only ever a CNOT control; Z_0 commutes with the chain
//    (only ever a control), so <Z_0> is unchanged by the CNOTs.
//  - <Z_0> = cos^2(t/2) - sin^2(t/2) = cos(t),  t = x[b,0] + w[0].
//
// R12 conclusion: dur = 5.376us across every fetch mechanism, cache policy,
// MLP shape, and instruction count => platform floor (9MB of irreducible
// sector traffic at the ~1.5TB/s burst-effective bandwidth of uncontrolled
// clocks). Traffic is minimal: one 32B sector per output, 8MB read + 1MB
// write. This round: last shape experiment — 128-thread CTAs (2048 blocks)
// for finer ramp/drain granularity; otherwise the proven minimal kernel.

__global__ __launch_bounds__(128)
void quantum_layer_kernel(const float* __restrict__ x,
                          const float* __restrict__ w,
                          float* __restrict__ out)
{
    const int b = blockIdx.x * 128 + threadIdx.x;   // exact cover, no check
    const float a  = __ldg(x + (size_t)b * 8);      // one 32B row-sector
    const float w0 = __ldg(w);                       // broadcast, cache-hit
    out[b] = __cosf(a + w0);
}

// Safety fallback for unexpected sizes (not hit for B=262144).
__global__ __launch_bounds__(128)
void quantum_layer_scalar(const float* __restrict__ x,
                          const float* __restrict__ w,
                          float* __restrict__ out, int B)
{
    const float w0 = __ldg(w);
    int b = blockIdx.x * blockDim.x + threadIdx.x;
    if (b < B) out[b] = __cosf(__ldg(x + (size_t)b * 8) + w0);
}

extern "C" void kernel_launch(void* const* d_in, const int* in_sizes, int n_in,
                              void* d_out, int out_size)
{
    const float* x = (const float*)d_in[0];   // [B, 8] float32
    const float* w = (const float*)d_in[1];   // [8]   float32
    float* out = (float*)d_out;               // [B]   float32
    int B = out_size;

    if ((B & 127) == 0) {
        quantum_layer_kernel<<<B / 128, 128>>>(x, w, out);   // 2048 CTAs
    } else {
        quantum_layer_scalar<<<(B + 127) / 128, 128>>>(x, w, out, B);
    }
}

// round 14
// speedup vs baseline: 1.0196x; 1.0196x over previous
#include <cuda_runtime.h>

// QuantumLayer collapses analytically to out[b] = cos(x[b,0] + weights[0]):
//  - The two RY layers compose: RY(w)RY(x)|0> = RY(x+w)|0>, leaving a
//    product state with qubit q at angle t_q = x[b,q] + w[q].
//  - Qubit 0 (the measured qubit) is only ever a CNOT *control*; Z_0
//    commutes with CNOT(0,1), and the rest of the chain acts on qubits >= 1,
//    so the CNOT layer does not change <Z_0>.
//  - <Z_0> = cos^2(t_0/2) - sin^2(t_0/2) = cos(t_0) = cos(x[b,0] + w[0]).
//
// Performance summary (rounds 2-13): traffic is irreducible at one 32B
// sector per output (8MB read + 1MB write); duration = 9MB / ~1.5TB/s
// burst-effective bandwidth in EVERY configuration tried (wave balance,
// occupancy 11-67%, MLP 1/2/8, block 128/256, LDG/LDG.256/TMA,
// .cs/evict_last/.L2::256B/default, 4-instr vs 20-instr bodies).
// => platform floor. This is the measured-best configuration: 1024 CTAs x
// 256 threads, exact cover, minimal straight-line body.

__global__ __launch_bounds__(256)
void quantum_layer_kernel(const float* __restrict__ x,
                          const float* __restrict__ w,
                          float* __restrict__ out)
{
    const int b = blockIdx.x * 256 + threadIdx.x;   // exact cover, no check
    const float a  = __ldg(x + (size_t)b * 8);      // one 32B row-sector
    const float w0 = __ldg(w);                       // broadcast, cache-hit
    out[b] = __cosf(a + w0);
}

// Safety fallback for unexpected sizes (not hit for B=262144).
__global__ __launch_bounds__(256)
void quantum_layer_scalar(const float* __restrict__ x,
                          const float* __restrict__ w,
                          float* __restrict__ out, int B)
{
    const float w0 = __ldg(w);
    int b = blockIdx.x * blockDim.x + threadIdx.x;
    if (b < B) out[b] = __cosf(__ldg(x + (size_t)b * 8) + w0);
}

extern "C" void kernel_launch(void* const* d_in, const int* in_sizes, int n_in,
                              void* d_out, int out_size)
{
    const float* x = (const float*)d_in[0];   // [B, 8] float32
    const float* w = (const float*)d_in[1];   // [8]   float32
    float* out = (float*)d_out;               // [B]   float32
    int B = out_size;

    if ((B & 255) == 0) {
        quantum_layer_kernel<<<B / 256, 256>>>(x, w, out);   // 1024 CTAs
    } else {
        quantum_layer_scalar<<<(B + 255) / 256, 256>>>(x, w, out, B);
    }
}

// round 15
// speedup vs baseline: 1.0297x; 1.0099x over previous
#include <cuda_runtime.h>

// QuantumLayer collapses analytically to out[b] = cos(x[b,0] + weights[0]):
//  - The two RY layers compose: RY(w)RY(x)|0> = RY(x+w)|0>, leaving a
//    product state with qubit q at angle t_q = x[b,q] + w[q].
//  - Qubit 0 (the measured qubit) is only ever a CNOT *control*; Z_0
//    commutes with CNOT(0,1), and the rest of the chain acts on qubits >= 1,
//    so the CNOT layer does not change <Z_0>.
//  - <Z_0> = cos^2(t_0/2) - sin^2(t_0/2) = cos(t_0) = cos(x[b,0] + w[0]).
//
// Performance summary (rounds 2-14): traffic is irreducible at one 32B
// sector per output (8MB read + 1MB write); duration = 9MB / ~1.5TB/s
// burst-effective bandwidth in EVERY configuration tried (wave balance,
// occupancy 11-67%, MLP 1/2/8, block 128/256, LDG/LDG.256/TMA,
// .cs/evict_last/.L2::256B/default, 4-instr vs 20-instr bodies); run-to-run
// noise is +-0.2us. => platform floor. This is the measured-best
// configuration (6.528us harness): 1024 CTAs x 256 threads, exact cover,
// minimal straight-line body, default caching.

__global__ __launch_bounds__(256)
void quantum_layer_kernel(const float* __restrict__ x,
                          const float* __restrict__ w,
                          float* __restrict__ out)
{
    const int b = blockIdx.x * 256 + threadIdx.x;   // exact cover, no check
    const float a  = __ldg(x + (size_t)b * 8);      // one 32B row-sector
    const float w0 = __ldg(w);                       // broadcast, cache-hit
    out[b] = __cosf(a + w0);
}

// Safety fallback for unexpected sizes (not hit for B=262144).
__global__ __launch_bounds__(256)
void quantum_layer_scalar(const float* __restrict__ x,
                          const float* __restrict__ w,
                          float* __restrict__ out, int B)
{
    const float w0 = __ldg(w);
    int b = blockIdx.x * blockDim.x + threadIdx.x;
    if (b < B) out[b] = __cosf(__ldg(x + (size_t)b * 8) + w0);
}

extern "C" void kernel_launch(void* const* d_in, const int* in_sizes, int n_in,
                              void* d_out, int out_size)
{
    const float* x = (const float*)d_in[0];   // [B, 8] float32
    const float* w = (const float*)d_in[1];   // [8]   float32
    float* out = (float*)d_out;               // [B]   float32
    int B = out_size;

    if ((B & 255) == 0) {
        quantum_layer_kernel<<<B / 256, 256>>>(x, w, out);   // 1024 CTAs
    } else {
        quantum_layer_scalar<<<(B + 255) / 256, 256>>>(x, w, out, B);
    }
}